// round 6
// baseline (speedup 1.0000x reference)
#include <cuda_runtime.h>
#include <stdint.h>

// Gaussian splatting preprocess.
// R6: 4 consecutive points per thread; ALL inputs via float4 loads (14 x
//     LDG.128, issued up front) and scalar output regions via float4 stores.
//     Kills the stride-3 L1 wavefront replay that capped R5.

__device__ __forceinline__ float scalar_to_float(const int* p) {
    int v = __ldg(p);
    if (v >= 0 && v < (1 << 23)) return (float)v;
    return __int_as_float(v);
}

struct Params {
    float fx, fy, fw, fh, rtile, clipX, clipY;
    int max_tx, max_ty;
};

struct ScalarOut {
    float tiles, tlx, tly, brx, bry, mask;
};

__device__ __forceinline__ ScalarOut process_point(
    float p0, float p1, float p2, float4 q,
    float s0, float s1, float s2,
    float c0, float c1, float c2, float op,
    int i, const float* __restrict__ E, const float* __restrict__ I,
    const Params& pr, float* __restrict__ out)
{
    // ---- quaternion -> rotation ----
    const float qn = rsqrtf(q.x*q.x + q.y*q.y + q.z*q.z + q.w*q.w);
    const float r  = q.x * qn;
    const float qx = q.y * qn;
    const float qy = q.z * qn;
    const float qz = q.w * qn;

    const float M00 = (1.0f - 2.0f*(qy*qy + qz*qz)) * s0;
    const float M01 = (2.0f*(qx*qy - r*qz))         * s1;
    const float M02 = (2.0f*(qx*qz + r*qy))         * s2;
    const float M10 = (2.0f*(qx*qy + r*qz))         * s0;
    const float M11 = (1.0f - 2.0f*(qx*qx + qz*qz)) * s1;
    const float M12 = (2.0f*(qy*qz - r*qx))         * s2;
    const float M20 = (2.0f*(qx*qz - r*qy))         * s0;
    const float M21 = (2.0f*(qy*qz + r*qx))         * s1;
    const float M22 = (1.0f - 2.0f*(qx*qx + qy*qy)) * s2;

    const float S00 = M00*M00 + M01*M01 + M02*M02;
    const float S01 = M00*M10 + M01*M11 + M02*M12;
    const float S02 = M00*M20 + M01*M21 + M02*M22;
    const float S11 = M10*M10 + M11*M11 + M12*M12;
    const float S12 = M10*M20 + M11*M21 + M12*M22;
    const float S22 = M20*M20 + M21*M21 + M22*M22;

    // pc = [p,1] @ E
    const float pc0 = p0*__ldg(E+0) + p1*__ldg(E+4) + p2*__ldg(E+8)  + __ldg(E+12);
    const float pc1 = p0*__ldg(E+1) + p1*__ldg(E+5) + p2*__ldg(E+9)  + __ldg(E+13);
    const float pc2 = p0*__ldg(E+2) + p1*__ldg(E+6) + p2*__ldg(E+10) + __ldg(E+14);
    const float pc3 = p0*__ldg(E+3) + p1*__ldg(E+7) + p2*__ldg(E+11) + __ldg(E+15);

    const float zc    = pc2;
    const bool  zmask = (zc > 0.2f);
    const float zs    = zmask ? zc : 1.0f;
    const float rz    = 1.0f / zs;

    const float xv = fminf(fmaxf(pc0 * rz, -pr.clipX), pr.clipX) * zc;
    const float yv = fminf(fmaxf(pc1 * rz, -pr.clipY), pr.clipY) * zc;

    const float j00 = pr.fx * rz;
    const float j11 = pr.fy * rz;
    const float rz2 = rz * rz;
    const float j02 = -(pr.fx * xv) * rz2;
    const float j12 = -(pr.fy * yv) * rz2;

    const float t00 = __ldg(E+0)*j00 + __ldg(E+2)*j02;
    const float t01 = __ldg(E+4)*j00 + __ldg(E+6)*j02;
    const float t02 = __ldg(E+8)*j00 + __ldg(E+10)*j02;
    const float t10 = __ldg(E+1)*j11 + __ldg(E+2)*j12;
    const float t11 = __ldg(E+5)*j11 + __ldg(E+6)*j12;
    const float t12 = __ldg(E+9)*j11 + __ldg(E+10)*j12;

    const float u0 = S00*t00 + S01*t01 + S02*t02;
    const float u1 = S01*t00 + S11*t01 + S12*t02;
    const float u2 = S02*t00 + S12*t01 + S22*t02;
    const float v0 = S00*t10 + S01*t11 + S02*t12;
    const float v1 = S01*t10 + S11*t11 + S12*t12;
    const float v2 = S02*t10 + S12*t11 + S22*t12;

    const float a = t00*u0 + t01*u1 + t02*u2 + 0.3f;
    const float b = t10*u0 + t11*u1 + t12*u2;
    const float d = t10*v0 + t11*v1 + t12*v2 + 0.3f;

    // ndc = pc @ I
    const float n0 = pc0*__ldg(I+0) + pc1*__ldg(I+4) + pc2*__ldg(I+8)  + pc3*__ldg(I+12);
    const float n1 = pc0*__ldg(I+1) + pc1*__ldg(I+5) + pc2*__ldg(I+9)  + pc3*__ldg(I+13);
    const float n2 = pc0*__ldg(I+2) + pc1*__ldg(I+6) + pc2*__ldg(I+10) + pc3*__ldg(I+14);
    const float n3 = pc0*__ldg(I+3) + pc1*__ldg(I+7) + pc2*__ldg(I+11) + pc3*__ldg(I+15);

    const float rw = 1.0f / (zmask ? n3 : 1.0f);
    const float nx = n0 * rw;
    const float ny = n1 * rw;
    const float nz = n2;

    const bool mask = (nz > 0.2f) && (nx < 1.3f) && (nx > -1.3f)
                                  && (ny < 1.3f) && (ny > -1.3f);

    const float det  = a*d - b*b;
    const float dets = (fabsf(det) < 1e-12f) ? 1e-12f : det;
    const float idet = 1.0f / dets;

    const float mid  = 0.5f * (a + d);
    const float sv   = sqrtf(fmaxf(mid*mid - det, 0.1f));
    const float radius = ceilf(3.0f * sqrtf(fmaxf(mid + sv, 1e-6f)));

    const float px = ((nx + 1.0f) * pr.fw - 1.0f) * 0.5f;
    const float py = ((ny + 1.0f) * pr.fh - 1.0f) * 0.5f;

    int tlx = (int)((px - radius) * pr.rtile);
    int tly = (int)((py - radius) * pr.rtile);
    int brx = (int)((px + radius) * pr.rtile);
    int bry = (int)((py + radius) * pr.rtile);
    tlx = min(max(tlx, 0), pr.max_tx);
    tly = min(max(tly, 0), pr.max_ty);
    brx = min(max(brx, 0), pr.max_tx);
    bry = min(max(bry, 0), pr.max_ty);

    const int span  = max(brx + 1 - tlx, 1) * max(bry + 1 - tly, 1);
    const int tiles = mask ? span : 0;

    float4 f0, f1, f2, f3;
    if (mask) {
        f0 = make_float4(px, py, nz, a);
        f1 = make_float4(b, b, d, d * idet);
        f2 = make_float4(-b * idet, -b * idet, a * idet, radius);
        f3 = make_float4(c0, c1, c2, op);
    } else {
        f0 = make_float4(0.f, 0.f, 0.f, 0.f);
        f1 = f0; f2 = f0; f3 = f0;
    }

    float4* o4 = reinterpret_cast<float4*>(out) + (size_t)i * 4;
    o4[0] = f0; o4[1] = f1; o4[2] = f2; o4[3] = f3;

    ScalarOut so;
    so.tiles = (float)tiles;
    so.tlx = (float)tlx;  so.tly = (float)tly;
    so.brx = (float)brx;  so.bry = (float)bry;
    so.mask = mask ? 1.0f : 0.0f;
    return so;
}

__global__ __launch_bounds__(128, 5)
void gs_pre_kernel(const float* __restrict__ points,
                   const float* __restrict__ quats,
                   const float* __restrict__ scales,
                   const float* __restrict__ colors,
                   const float* __restrict__ opacity,
                   const float* __restrict__ E,
                   const float* __restrict__ I,
                   const int* __restrict__ p_fx,
                   const int* __restrict__ p_fy,
                   const int* __restrict__ p_w,
                   const int* __restrict__ p_h,
                   const int* __restrict__ p_tile,
                   float* __restrict__ out,
                   int n)
{
    const int gid = blockIdx.x * blockDim.x + threadIdx.x;
    const int b   = gid * 4;
    if (b >= n) return;

    Params pr;
    pr.fx = scalar_to_float(p_fx);
    pr.fy = scalar_to_float(p_fy);
    pr.fw = scalar_to_float(p_w);
    pr.fh = scalar_to_float(p_h);
    const float tile = scalar_to_float(p_tile);
    pr.rtile = 1.0f / tile;                       // tile = 16 -> exact
    pr.clipX = 1.3f * (pr.fw / (2.0f * pr.fx));
    pr.clipY = 1.3f * (pr.fh / (2.0f * pr.fy));
    pr.max_tx = (int)ceilf(pr.fw * pr.rtile) - 1;
    pr.max_ty = (int)ceilf(pr.fh * pr.rtile) - 1;
    const size_t N = (size_t)n;

    if (b + 4 <= n) {
        // ---- fast path: all-vector loads, issued back-to-back ----
        const float4* P4 = reinterpret_cast<const float4*>(points);
        const float4* S4 = reinterpret_cast<const float4*>(scales);
        const float4* C4 = reinterpret_cast<const float4*>(colors);
        const float4* Q4 = reinterpret_cast<const float4*>(quats);
        const float4* O4 = reinterpret_cast<const float4*>(opacity);

        const float4 P0 = __ldg(P4 + 3*gid + 0);
        const float4 P1 = __ldg(P4 + 3*gid + 1);
        const float4 P2 = __ldg(P4 + 3*gid + 2);
        const float4 Q0 = __ldg(Q4 + b + 0);
        const float4 Q1 = __ldg(Q4 + b + 1);
        const float4 Q2 = __ldg(Q4 + b + 2);
        const float4 Q3 = __ldg(Q4 + b + 3);
        const float4 S0 = __ldg(S4 + 3*gid + 0);
        const float4 S1 = __ldg(S4 + 3*gid + 1);
        const float4 S2 = __ldg(S4 + 3*gid + 2);
        const float4 C0 = __ldg(C4 + 3*gid + 0);
        const float4 C1 = __ldg(C4 + 3*gid + 1);
        const float4 C2 = __ldg(C4 + 3*gid + 2);
        const float4 OP = __ldg(O4 + gid);

        ScalarOut so0 = process_point(P0.x, P0.y, P0.z, Q0, S0.x, S0.y, S0.z,
                                      C0.x, C0.y, C0.z, OP.x, b+0, E, I, pr, out);
        ScalarOut so1 = process_point(P0.w, P1.x, P1.y, Q1, S0.w, S1.x, S1.y,
                                      C0.w, C1.x, C1.y, OP.y, b+1, E, I, pr, out);
        ScalarOut so2 = process_point(P1.z, P1.w, P2.x, Q2, S1.z, S1.w, S2.x,
                                      C1.z, C1.w, C2.x, OP.z, b+2, E, I, pr, out);
        ScalarOut so3 = process_point(P2.y, P2.z, P2.w, Q3, S2.y, S2.z, S2.w,
                                      C2.y, C2.z, C2.w, OP.w, b+3, E, I, pr, out);

        if ((n & 3) == 0) {
            // All six scalar regions are 16B-aligned at index b.
            *reinterpret_cast<float4*>(out + 16*N + b) = make_float4(so0.tiles, so1.tiles, so2.tiles, so3.tiles);
            *reinterpret_cast<float4*>(out + 17*N + b) = make_float4(so0.tlx, so1.tlx, so2.tlx, so3.tlx);
            *reinterpret_cast<float4*>(out + 18*N + b) = make_float4(so0.tly, so1.tly, so2.tly, so3.tly);
            *reinterpret_cast<float4*>(out + 19*N + b) = make_float4(so0.brx, so1.brx, so2.brx, so3.brx);
            *reinterpret_cast<float4*>(out + 20*N + b) = make_float4(so0.bry, so1.bry, so2.bry, so3.bry);
            *reinterpret_cast<float4*>(out + 21*N + b) = make_float4(so0.mask, so1.mask, so2.mask, so3.mask);
        } else {
            const ScalarOut so[4] = {so0, so1, so2, so3};
#pragma unroll
            for (int j = 0; j < 4; j++) {
                out[16*N + b + j] = so[j].tiles;
                out[17*N + b + j] = so[j].tlx;
                out[18*N + b + j] = so[j].tly;
                out[19*N + b + j] = so[j].brx;
                out[20*N + b + j] = so[j].bry;
                out[21*N + b + j] = so[j].mask;
            }
        }
    } else {
        // ---- tail: scalar loads/stores, per point ----
        for (int i = b; i < n; i++) {
            const float  p0 = __ldg(points + 3*i + 0);
            const float  p1 = __ldg(points + 3*i + 1);
            const float  p2 = __ldg(points + 3*i + 2);
            const float4 q  = __ldg(reinterpret_cast<const float4*>(quats) + i);
            const float  s0 = __ldg(scales + 3*i + 0);
            const float  s1 = __ldg(scales + 3*i + 1);
            const float  s2 = __ldg(scales + 3*i + 2);
            const float  c0 = __ldg(colors + 3*i + 0);
            const float  c1 = __ldg(colors + 3*i + 1);
            const float  c2 = __ldg(colors + 3*i + 2);
            const float  op = __ldg(opacity + i);
            ScalarOut so = process_point(p0, p1, p2, q, s0, s1, s2,
                                         c0, c1, c2, op, i, E, I, pr, out);
            out[16*N + i] = so.tiles;
            out[17*N + i] = so.tlx;
            out[18*N + i] = so.tly;
            out[19*N + i] = so.brx;
            out[20*N + i] = so.bry;
            out[21*N + i] = so.mask;
        }
    }
}

extern "C" void kernel_launch(void* const* d_in, const int* in_sizes, int n_in,
                              void* d_out, int out_size)
{
    const float* points  = (const float*)d_in[0];
    const float* quats   = (const float*)d_in[1];
    const float* scales  = (const float*)d_in[2];
    const float* colors  = (const float*)d_in[3];
    const float* opacity = (const float*)d_in[4];
    const float* E       = (const float*)d_in[5];
    const float* I       = (const float*)d_in[6];
    const int*   p_fx    = (const int*)d_in[7];
    const int*   p_fy    = (const int*)d_in[8];
    const int*   p_w     = (const int*)d_in[9];
    const int*   p_h     = (const int*)d_in[10];
    const int*   p_tile  = (const int*)d_in[11];

    const int n = in_sizes[0] / 3;
    float* out = (float*)d_out;

    const int threads = 128;
    const int per_block = threads * 4;
    const int blocks = (n + per_block - 1) / per_block;
    gs_pre_kernel<<<blocks, threads>>>(points, quats, scales, colors, opacity,
                                       E, I, p_fx, p_fy, p_w, p_h, p_tile,
                                       out, n);
}

// round 7
// speedup vs baseline: 1.0680x; 1.0680x over previous
#include <cuda_runtime.h>
#include <stdint.h>

// Gaussian splatting preprocess.
// R7: R5 ILP-2 structure + E/I/scalars moved to __constant__ memory
//     (graph-capturable D2D cudaMemcpyToSymbolAsync), removing ~32 uniform
//     L1 loads per thread from the LSU path. launch_bounds(128,10)=48 regs.

__constant__ float cE[16];
__constant__ float cI[16];
__constant__ int   cScal[5];   // fx, fy, w, h, tile (int32 or float32 bits)

__device__ __forceinline__ float scal(int k) {
    int v = cScal[k];
    if (v >= 0 && v < (1 << 23)) return (float)v;
    return __int_as_float(v);
}

struct PtIn {
    float p0, p1, p2;
    float4 q;
    float s0, s1, s2;
};

__device__ __forceinline__ PtIn load_point(const float* __restrict__ points,
                                           const float* __restrict__ quats,
                                           const float* __restrict__ scales,
                                           int i)
{
    PtIn v;
    v.p0 = __ldg(points + 3*i + 0);
    v.p1 = __ldg(points + 3*i + 1);
    v.p2 = __ldg(points + 3*i + 2);
    v.q  = __ldg(reinterpret_cast<const float4*>(quats) + i);
    v.s0 = __ldg(scales + 3*i + 0);
    v.s1 = __ldg(scales + 3*i + 1);
    v.s2 = __ldg(scales + 3*i + 2);
    return v;
}

__device__ __forceinline__ void process_point(
    const PtIn& in, int i, size_t N,
    const float* __restrict__ colors, const float* __restrict__ opacity,
    float fx, float fy, float fw, float fh, float rtile,
    float clipX, float clipY, int max_tx, int max_ty,
    float* __restrict__ out)
{
    // Store-time loads issued first; the math below hides them.
    const float c0 = __ldg(colors + 3*i + 0);
    const float c1 = __ldg(colors + 3*i + 1);
    const float c2 = __ldg(colors + 3*i + 2);
    const float op = __ldg(opacity + i);

    // ---- quaternion -> rotation ----
    const float4 q = in.q;
    const float qn = rsqrtf(q.x*q.x + q.y*q.y + q.z*q.z + q.w*q.w);
    const float r  = q.x * qn;
    const float qx = q.y * qn;
    const float qy = q.z * qn;
    const float qz = q.w * qn;

    const float M00 = (1.0f - 2.0f*(qy*qy + qz*qz)) * in.s0;
    const float M01 = (2.0f*(qx*qy - r*qz))         * in.s1;
    const float M02 = (2.0f*(qx*qz + r*qy))         * in.s2;
    const float M10 = (2.0f*(qx*qy + r*qz))         * in.s0;
    const float M11 = (1.0f - 2.0f*(qx*qx + qz*qz)) * in.s1;
    const float M12 = (2.0f*(qy*qz - r*qx))         * in.s2;
    const float M20 = (2.0f*(qx*qz - r*qy))         * in.s0;
    const float M21 = (2.0f*(qy*qz + r*qx))         * in.s1;
    const float M22 = (1.0f - 2.0f*(qx*qx + qy*qy)) * in.s2;

    const float S00 = M00*M00 + M01*M01 + M02*M02;
    const float S01 = M00*M10 + M01*M11 + M02*M12;
    const float S02 = M00*M20 + M01*M21 + M02*M22;
    const float S11 = M10*M10 + M11*M11 + M12*M12;
    const float S12 = M10*M20 + M11*M21 + M12*M22;
    const float S22 = M20*M20 + M21*M21 + M22*M22;

    // pc = [p,1] @ E
    const float pc0 = in.p0*cE[0] + in.p1*cE[4] + in.p2*cE[8]  + cE[12];
    const float pc1 = in.p0*cE[1] + in.p1*cE[5] + in.p2*cE[9]  + cE[13];
    const float pc2 = in.p0*cE[2] + in.p1*cE[6] + in.p2*cE[10] + cE[14];
    const float pc3 = in.p0*cE[3] + in.p1*cE[7] + in.p2*cE[11] + cE[15];

    const float zc    = pc2;
    const bool  zmask = (zc > 0.2f);
    const float zs    = zmask ? zc : 1.0f;
    const float rz    = 1.0f / zs;

    const float xv = fminf(fmaxf(pc0 * rz, -clipX), clipX) * zc;
    const float yv = fminf(fmaxf(pc1 * rz, -clipY), clipY) * zc;

    const float j00 = fx * rz;
    const float j11 = fy * rz;
    const float rz2 = rz * rz;
    const float j02 = -(fx * xv) * rz2;
    const float j12 = -(fy * yv) * rz2;

    const float t00 = cE[0]*j00 + cE[2]*j02;
    const float t01 = cE[4]*j00 + cE[6]*j02;
    const float t02 = cE[8]*j00 + cE[10]*j02;
    const float t10 = cE[1]*j11 + cE[2]*j12;
    const float t11 = cE[5]*j11 + cE[6]*j12;
    const float t12 = cE[9]*j11 + cE[10]*j12;

    const float u0 = S00*t00 + S01*t01 + S02*t02;
    const float u1 = S01*t00 + S11*t01 + S12*t02;
    const float u2 = S02*t00 + S12*t01 + S22*t02;
    const float v0 = S00*t10 + S01*t11 + S02*t12;
    const float v1 = S01*t10 + S11*t11 + S12*t12;
    const float v2 = S02*t10 + S12*t11 + S22*t12;

    const float a = t00*u0 + t01*u1 + t02*u2 + 0.3f;
    const float b = t10*u0 + t11*u1 + t12*u2;
    const float d = t10*v0 + t11*v1 + t12*v2 + 0.3f;

    // ndc = pc @ I
    const float n0 = pc0*cI[0] + pc1*cI[4] + pc2*cI[8]  + pc3*cI[12];
    const float n1 = pc0*cI[1] + pc1*cI[5] + pc2*cI[9]  + pc3*cI[13];
    const float n2 = pc0*cI[2] + pc1*cI[6] + pc2*cI[10] + pc3*cI[14];
    const float n3 = pc0*cI[3] + pc1*cI[7] + pc2*cI[11] + pc3*cI[15];

    const float rw = 1.0f / (zmask ? n3 : 1.0f);
    const float nx = n0 * rw;
    const float ny = n1 * rw;
    const float nz = n2;

    const bool mask = (nz > 0.2f) && (nx < 1.3f) && (nx > -1.3f)
                                  && (ny < 1.3f) && (ny > -1.3f);

    const float det  = a*d - b*b;
    const float dets = (fabsf(det) < 1e-12f) ? 1e-12f : det;
    const float idet = 1.0f / dets;

    const float mid  = 0.5f * (a + d);
    const float sv   = sqrtf(fmaxf(mid*mid - det, 0.1f));
    const float radius = ceilf(3.0f * sqrtf(fmaxf(mid + sv, 1e-6f)));

    const float px = ((nx + 1.0f) * fw - 1.0f) * 0.5f;
    const float py = ((ny + 1.0f) * fh - 1.0f) * 0.5f;

    int tlx = (int)((px - radius) * rtile);
    int tly = (int)((py - radius) * rtile);
    int brx = (int)((px + radius) * rtile);
    int bry = (int)((py + radius) * rtile);
    tlx = min(max(tlx, 0), max_tx);
    tly = min(max(tly, 0), max_ty);
    brx = min(max(brx, 0), max_tx);
    bry = min(max(bry, 0), max_ty);

    const int span  = max(brx + 1 - tlx, 1) * max(bry + 1 - tly, 1);
    const int tiles = mask ? span : 0;

    float4 f0, f1, f2, f3;
    if (mask) {
        f0 = make_float4(px, py, nz, a);
        f1 = make_float4(b, b, d, d * idet);
        f2 = make_float4(-b * idet, -b * idet, a * idet, radius);
        f3 = make_float4(c0, c1, c2, op);
    } else {
        f0 = make_float4(0.f, 0.f, 0.f, 0.f);
        f1 = f0; f2 = f0; f3 = f0;
    }

    float4* o4 = reinterpret_cast<float4*>(out) + (size_t)i * 4;
    o4[0] = f0; o4[1] = f1; o4[2] = f2; o4[3] = f3;

    out[16*N + i] = (float)tiles;
    out[17*N + i] = (float)tlx;
    out[18*N + i] = (float)tly;
    out[19*N + i] = (float)brx;
    out[20*N + i] = (float)bry;
    out[21*N + i] = mask ? 1.0f : 0.0f;
}

__global__ __launch_bounds__(128, 10)
void gs_pre_kernel(const float* __restrict__ points,
                   const float* __restrict__ quats,
                   const float* __restrict__ scales,
                   const float* __restrict__ colors,
                   const float* __restrict__ opacity,
                   float* __restrict__ out,
                   int n)
{
    const int stride = gridDim.x * blockDim.x;
    int i = blockIdx.x * blockDim.x + threadIdx.x;
    if (i >= n) return;

    const float fx   = scal(0);
    const float fy   = scal(1);
    const float fw   = scal(2);
    const float fh   = scal(3);
    const float tile = scal(4);
    const float rtile = 1.0f / tile;                 // tile = 16 -> exact
    const float clipX = 1.3f * (fw / (2.0f * fx));
    const float clipY = 1.3f * (fh / (2.0f * fy));
    const int max_tx = (int)ceilf(fw * rtile) - 1;
    const int max_ty = (int)ceilf(fh * rtile) - 1;
    const size_t N = (size_t)n;

    PtIn cur = load_point(points, quats, scales, i);

    const int i1 = i + stride;
    const bool has1 = (i1 < n);
    PtIn nxt = load_point(points, quats, scales, has1 ? i1 : i);

    process_point(cur, i, N, colors, opacity,
                  fx, fy, fw, fh, rtile, clipX, clipY, max_tx, max_ty, out);

    if (has1) {
        process_point(nxt, i1, N, colors, opacity,
                      fx, fy, fw, fh, rtile, clipX, clipY, max_tx, max_ty, out);
    }
}

extern "C" void kernel_launch(void* const* d_in, const int* in_sizes, int n_in,
                              void* d_out, int out_size)
{
    const float* points  = (const float*)d_in[0];
    const float* quats   = (const float*)d_in[1];
    const float* scales  = (const float*)d_in[2];
    const float* colors  = (const float*)d_in[3];
    const float* opacity = (const float*)d_in[4];

    // Per-launch constants -> constant memory (D2D async copies are
    // graph-capturable memcpy nodes).
    cudaMemcpyToSymbolAsync(cE, d_in[5], 16 * sizeof(float), 0,
                            cudaMemcpyDeviceToDevice);
    cudaMemcpyToSymbolAsync(cI, d_in[6], 16 * sizeof(float), 0,
                            cudaMemcpyDeviceToDevice);
    for (int k = 0; k < 5; k++) {
        cudaMemcpyToSymbolAsync(cScal, d_in[7 + k], sizeof(int),
                                k * sizeof(int), cudaMemcpyDeviceToDevice);
    }

    const int n = in_sizes[0] / 3;
    float* out = (float*)d_out;

    const int threads = 128;
    const int blocks  = (n + threads * 2 - 1) / (threads * 2);
    gs_pre_kernel<<<blocks, threads>>>(points, quats, scales, colors, opacity,
                                       out, n);
}

// round 8
// speedup vs baseline: 1.2334x; 1.1548x over previous
#include <cuda_runtime.h>
#include <stdint.h>

// Gaussian splatting preprocess.
// R8: R7's fast kernel body, but E/I delivered via per-block __shared__
//     staging (32 floats, one warp, one barrier) instead of graph memcpy
//     nodes — keeps the total graph at a single kernel node.
//     ILP-2 pipeline, launch_bounds(128,10)=48 regs.

__device__ __forceinline__ float scalar_to_float(const int* p) {
    int v = __ldg(p);
    if (v >= 0 && v < (1 << 23)) return (float)v;
    return __int_as_float(v);
}

struct PtIn {
    float p0, p1, p2;
    float4 q;
    float s0, s1, s2;
};

__device__ __forceinline__ PtIn load_point(const float* __restrict__ points,
                                           const float* __restrict__ quats,
                                           const float* __restrict__ scales,
                                           int i)
{
    PtIn v;
    v.p0 = __ldg(points + 3*i + 0);
    v.p1 = __ldg(points + 3*i + 1);
    v.p2 = __ldg(points + 3*i + 2);
    v.q  = __ldg(reinterpret_cast<const float4*>(quats) + i);
    v.s0 = __ldg(scales + 3*i + 0);
    v.s1 = __ldg(scales + 3*i + 1);
    v.s2 = __ldg(scales + 3*i + 2);
    return v;
}

__device__ __forceinline__ void process_point(
    const PtIn& in, int i, size_t N,
    const float* __restrict__ colors, const float* __restrict__ opacity,
    const float* sE, const float* sI,
    float fx, float fy, float fw, float fh, float rtile,
    float clipX, float clipY, int max_tx, int max_ty,
    float* __restrict__ out)
{
    // Store-time loads issued first; the math below hides them.
    const float c0 = __ldg(colors + 3*i + 0);
    const float c1 = __ldg(colors + 3*i + 1);
    const float c2 = __ldg(colors + 3*i + 2);
    const float op = __ldg(opacity + i);

    // ---- quaternion -> rotation ----
    const float4 q = in.q;
    const float qn = rsqrtf(q.x*q.x + q.y*q.y + q.z*q.z + q.w*q.w);
    const float r  = q.x * qn;
    const float qx = q.y * qn;
    const float qy = q.z * qn;
    const float qz = q.w * qn;

    const float M00 = (1.0f - 2.0f*(qy*qy + qz*qz)) * in.s0;
    const float M01 = (2.0f*(qx*qy - r*qz))         * in.s1;
    const float M02 = (2.0f*(qx*qz + r*qy))         * in.s2;
    const float M10 = (2.0f*(qx*qy + r*qz))         * in.s0;
    const float M11 = (1.0f - 2.0f*(qx*qx + qz*qz)) * in.s1;
    const float M12 = (2.0f*(qy*qz - r*qx))         * in.s2;
    const float M20 = (2.0f*(qx*qz - r*qy))         * in.s0;
    const float M21 = (2.0f*(qy*qz + r*qx))         * in.s1;
    const float M22 = (1.0f - 2.0f*(qx*qx + qy*qy)) * in.s2;

    const float S00 = M00*M00 + M01*M01 + M02*M02;
    const float S01 = M00*M10 + M01*M11 + M02*M12;
    const float S02 = M00*M20 + M01*M21 + M02*M22;
    const float S11 = M10*M10 + M11*M11 + M12*M12;
    const float S12 = M10*M20 + M11*M21 + M12*M22;
    const float S22 = M20*M20 + M21*M21 + M22*M22;

    // pc = [p,1] @ E
    const float pc0 = in.p0*sE[0] + in.p1*sE[4] + in.p2*sE[8]  + sE[12];
    const float pc1 = in.p0*sE[1] + in.p1*sE[5] + in.p2*sE[9]  + sE[13];
    const float pc2 = in.p0*sE[2] + in.p1*sE[6] + in.p2*sE[10] + sE[14];
    const float pc3 = in.p0*sE[3] + in.p1*sE[7] + in.p2*sE[11] + sE[15];

    const float zc    = pc2;
    const bool  zmask = (zc > 0.2f);
    const float zs    = zmask ? zc : 1.0f;
    const float rz    = 1.0f / zs;

    const float xv = fminf(fmaxf(pc0 * rz, -clipX), clipX) * zc;
    const float yv = fminf(fmaxf(pc1 * rz, -clipY), clipY) * zc;

    const float j00 = fx * rz;
    const float j11 = fy * rz;
    const float rz2 = rz * rz;
    const float j02 = -(fx * xv) * rz2;
    const float j12 = -(fy * yv) * rz2;

    const float t00 = sE[0]*j00 + sE[2]*j02;
    const float t01 = sE[4]*j00 + sE[6]*j02;
    const float t02 = sE[8]*j00 + sE[10]*j02;
    const float t10 = sE[1]*j11 + sE[2]*j12;
    const float t11 = sE[5]*j11 + sE[6]*j12;
    const float t12 = sE[9]*j11 + sE[10]*j12;

    const float u0 = S00*t00 + S01*t01 + S02*t02;
    const float u1 = S01*t00 + S11*t01 + S12*t02;
    const float u2 = S02*t00 + S12*t01 + S22*t02;
    const float v0 = S00*t10 + S01*t11 + S02*t12;
    const float v1 = S01*t10 + S11*t11 + S12*t12;
    const float v2 = S02*t10 + S12*t11 + S22*t12;

    const float a = t00*u0 + t01*u1 + t02*u2 + 0.3f;
    const float b = t10*u0 + t11*u1 + t12*u2;
    const float d = t10*v0 + t11*v1 + t12*v2 + 0.3f;

    // ndc = pc @ I
    const float n0 = pc0*sI[0] + pc1*sI[4] + pc2*sI[8]  + pc3*sI[12];
    const float n1 = pc0*sI[1] + pc1*sI[5] + pc2*sI[9]  + pc3*sI[13];
    const float n2 = pc0*sI[2] + pc1*sI[6] + pc2*sI[10] + pc3*sI[14];
    const float n3 = pc0*sI[3] + pc1*sI[7] + pc2*sI[11] + pc3*sI[15];

    const float rw = 1.0f / (zmask ? n3 : 1.0f);
    const float nx = n0 * rw;
    const float ny = n1 * rw;
    const float nz = n2;

    const bool mask = (nz > 0.2f) && (nx < 1.3f) && (nx > -1.3f)
                                  && (ny < 1.3f) && (ny > -1.3f);

    const float det  = a*d - b*b;
    const float dets = (fabsf(det) < 1e-12f) ? 1e-12f : det;
    const float idet = 1.0f / dets;

    const float mid  = 0.5f * (a + d);
    const float sv   = sqrtf(fmaxf(mid*mid - det, 0.1f));
    const float radius = ceilf(3.0f * sqrtf(fmaxf(mid + sv, 1e-6f)));

    const float px = ((nx + 1.0f) * fw - 1.0f) * 0.5f;
    const float py = ((ny + 1.0f) * fh - 1.0f) * 0.5f;

    int tlx = (int)((px - radius) * rtile);
    int tly = (int)((py - radius) * rtile);
    int brx = (int)((px + radius) * rtile);
    int bry = (int)((py + radius) * rtile);
    tlx = min(max(tlx, 0), max_tx);
    tly = min(max(tly, 0), max_ty);
    brx = min(max(brx, 0), max_tx);
    bry = min(max(bry, 0), max_ty);

    const int span  = max(brx + 1 - tlx, 1) * max(bry + 1 - tly, 1);
    const int tiles = mask ? span : 0;

    float4 f0, f1, f2, f3;
    if (mask) {
        f0 = make_float4(px, py, nz, a);
        f1 = make_float4(b, b, d, d * idet);
        f2 = make_float4(-b * idet, -b * idet, a * idet, radius);
        f3 = make_float4(c0, c1, c2, op);
    } else {
        f0 = make_float4(0.f, 0.f, 0.f, 0.f);
        f1 = f0; f2 = f0; f3 = f0;
    }

    float4* o4 = reinterpret_cast<float4*>(out) + (size_t)i * 4;
    o4[0] = f0; o4[1] = f1; o4[2] = f2; o4[3] = f3;

    out[16*N + i] = (float)tiles;
    out[17*N + i] = (float)tlx;
    out[18*N + i] = (float)tly;
    out[19*N + i] = (float)brx;
    out[20*N + i] = (float)bry;
    out[21*N + i] = mask ? 1.0f : 0.0f;
}

__global__ __launch_bounds__(128, 10)
void gs_pre_kernel(const float* __restrict__ points,
                   const float* __restrict__ quats,
                   const float* __restrict__ scales,
                   const float* __restrict__ colors,
                   const float* __restrict__ opacity,
                   const float* __restrict__ E,
                   const float* __restrict__ I,
                   const int* __restrict__ p_fx,
                   const int* __restrict__ p_fy,
                   const int* __restrict__ p_w,
                   const int* __restrict__ p_h,
                   const int* __restrict__ p_tile,
                   float* __restrict__ out,
                   int n)
{
    __shared__ float sE[16];
    __shared__ float sI[16];
    if (threadIdx.x < 16) {
        sE[threadIdx.x] = __ldg(E + threadIdx.x);
        sI[threadIdx.x] = __ldg(I + threadIdx.x);
    }
    __syncthreads();

    const int stride = gridDim.x * blockDim.x;
    int i = blockIdx.x * blockDim.x + threadIdx.x;
    if (i >= n) return;

    const float fx   = scalar_to_float(p_fx);
    const float fy   = scalar_to_float(p_fy);
    const float fw   = scalar_to_float(p_w);
    const float fh   = scalar_to_float(p_h);
    const float tile = scalar_to_float(p_tile);
    const float rtile = 1.0f / tile;                 // tile = 16 -> exact
    const float clipX = 1.3f * (fw / (2.0f * fx));
    const float clipY = 1.3f * (fh / (2.0f * fy));
    const int max_tx = (int)ceilf(fw * rtile) - 1;
    const int max_ty = (int)ceilf(fh * rtile) - 1;
    const size_t N = (size_t)n;

    PtIn cur = load_point(points, quats, scales, i);

    const int i1 = i + stride;
    const bool has1 = (i1 < n);
    PtIn nxt = load_point(points, quats, scales, has1 ? i1 : i);

    process_point(cur, i, N, colors, opacity, sE, sI,
                  fx, fy, fw, fh, rtile, clipX, clipY, max_tx, max_ty, out);

    if (has1) {
        process_point(nxt, i1, N, colors, opacity, sE, sI,
                      fx, fy, fw, fh, rtile, clipX, clipY, max_tx, max_ty, out);
    }
}

extern "C" void kernel_launch(void* const* d_in, const int* in_sizes, int n_in,
                              void* d_out, int out_size)
{
    const float* points  = (const float*)d_in[0];
    const float* quats   = (const float*)d_in[1];
    const float* scales  = (const float*)d_in[2];
    const float* colors  = (const float*)d_in[3];
    const float* opacity = (const float*)d_in[4];
    const float* E       = (const float*)d_in[5];
    const float* I       = (const float*)d_in[6];
    const int*   p_fx    = (const int*)d_in[7];
    const int*   p_fy    = (const int*)d_in[8];
    const int*   p_w     = (const int*)d_in[9];
    const int*   p_h     = (const int*)d_in[10];
    const int*   p_tile  = (const int*)d_in[11];

    const int n = in_sizes[0] / 3;
    float* out = (float*)d_out;

    const int threads = 128;
    const int blocks  = (n + threads * 2 - 1) / (threads * 2);
    gs_pre_kernel<<<blocks, threads>>>(points, quats, scales, colors, opacity,
                                       E, I, p_fx, p_fy, p_w, p_h, p_tile,
                                       out, n);
}